// round 10
// baseline (speedup 1.0000x reference)
#include <cuda_runtime.h>
#include <cuda_bf16.h>
#include <math_constants.h>

// AttentionMax: correlation[b,s] = <q[b], sub[b,s]>, argmax over s, one-hot out [bz, ns, 1]
// bz=4096, ns=256, d=128, fp32. Memory-bound: 512MB compulsory stream of feat_sub.
//
// R10: R9 inner shape (pipelined 4-row double buffer, deep prologue, multi-row
// shfl reduce, L2::256B streaming loads, streaming stores), but TWO batches per
// 512-thread CTA (warps 0-7 -> b0, warps 8-15 -> b1). Halves the 4096 CTA
// ramps/tails that R9 showed to be the residual elapsed-time dilution.

#define NS 256
#define D  128

__device__ __forceinline__ float4 ldcs256(const float4* p)
{
    float4 v;
    asm("ld.global.cs.L2::256B.v4.f32 {%0,%1,%2,%3}, [%4];"
        : "=f"(v.x), "=f"(v.y), "=f"(v.z), "=f"(v.w)
        : "l"(p));
    return v;
}

__device__ __forceinline__ void stcs(float* p, float v)
{
    asm volatile("st.global.cs.f32 [%0], %1;" :: "l"(p), "f"(v) : "memory");
}

// Fold 4 rows' per-lane partials into full row sums.
// Result: lane L holds sum of row base + ((L>>3)&3), replicated across 8 lanes.
__device__ __forceinline__ float reduce4(float p0, float p1, float p2, float p3,
                                         int lane)
{
    const unsigned FULL = 0xffffffffu;
    bool hi16 = (lane & 16) != 0;
    float s0 = hi16 ? p0 : p2;
    float s1 = hi16 ? p1 : p3;
    float r0 = __shfl_xor_sync(FULL, s0, 16);
    float r1 = __shfl_xor_sync(FULL, s1, 16);
    float a0 = (hi16 ? p2 : p0) + r0;
    float a1 = (hi16 ? p3 : p1) + r1;
    bool hi8 = (lane & 8) != 0;
    float s = hi8 ? a0 : a1;
    float r = __shfl_xor_sync(FULL, s, 8);
    float acc = (hi8 ? a1 : a0) + r;
    acc += __shfl_xor_sync(FULL, acc, 4);
    acc += __shfl_xor_sync(FULL, acc, 2);
    acc += __shfl_xor_sync(FULL, acc, 1);
    return acc;
}

__device__ __forceinline__ float dot4(float4 v, float4 q)
{
    float p = v.x * q.x;
    p = fmaf(v.y, q.y, p);
    p = fmaf(v.z, q.z, p);
    p = fmaf(v.w, q.w, p);
    return p;
}

__global__ __launch_bounds__(512, 2)
void attention_max_kernel(const float* __restrict__ q,
                          const float* __restrict__ sub,
                          float* __restrict__ out)
{
    const int tid   = threadIdx.x;
    const int warp  = tid >> 5;            // 0..15
    const int lane  = tid & 31;
    const int grp   = warp >> 3;           // 0: batch b0, 1: batch b1
    const int gwarp = warp & 7;            // warp within its batch group
    const int b     = blockIdx.x * 2 + grp;
    const int myrow = (lane >> 3) & 3;
    const unsigned FULL = 0xffffffffu;

    const float4* base = reinterpret_cast<const float4*>(
        sub + ((size_t)b * NS + gwarp * 32) * D);

    // Deep prologue: 8 row-loads in flight before any dependent work.
    float4 va[4], vb[4];
#pragma unroll
    for (int j = 0; j < 4; ++j)
        va[j] = ldcs256(&base[j * 32 + lane]);
#pragma unroll
    for (int j = 0; j < 4; ++j)
        vb[j] = ldcs256(&base[(4 + j) * 32 + lane]);

    const float4 qc = reinterpret_cast<const float4*>(q + (size_t)b * D)[lane];

    float bestv = -CUDART_INF_F;
    int   besti = 0;

#pragma unroll
    for (int rr = 0; rr < 32; rr += 8) {
        {
            float s = reduce4(dot4(va[0], qc), dot4(va[1], qc),
                              dot4(va[2], qc), dot4(va[3], qc), lane);
            if (s > bestv) { bestv = s; besti = gwarp * 32 + rr + myrow; }
        }

        if (rr + 8 < 32) {
#pragma unroll
            for (int j = 0; j < 4; ++j)
                va[j] = ldcs256(&base[(rr + 8 + j) * 32 + lane]);
        }

        {
            float s = reduce4(dot4(vb[0], qc), dot4(vb[1], qc),
                              dot4(vb[2], qc), dot4(vb[3], qc), lane);
            if (s > bestv) { bestv = s; besti = gwarp * 32 + rr + 4 + myrow; }
        }

        if (rr + 8 < 32) {
#pragma unroll
            for (int j = 0; j < 4; ++j)
                vb[j] = ldcs256(&base[(rr + 12 + j) * 32 + lane]);
        }
    }

    // Cross-lane argmax (value max, smaller index wins ties -> first occurrence).
#pragma unroll
    for (int m = 16; m > 0; m >>= 1) {
        float ov = __shfl_xor_sync(FULL, bestv, m);
        int   oi = __shfl_xor_sync(FULL, besti, m);
        if (ov > bestv || (ov == bestv && oi < besti)) { bestv = ov; besti = oi; }
    }

    __shared__ float wval[16];
    __shared__ int   widx[16];

    if (lane == 0) { wval[warp] = bestv; widx[warp] = besti; }
    __syncthreads();

    // Each thread reduces the 8 warp results of ITS batch group.
    const int gbase = grp * 8;
    float bv = wval[gbase];
    int   bi = widx[gbase];
#pragma unroll
    for (int w = 1; w < 8; ++w)
        if (wval[gbase + w] > bv) { bv = wval[gbase + w]; bi = widx[gbase + w]; }

    const int e = tid & 255;   // element index within this batch's one-hot row
    stcs(out + (size_t)b * NS + e, (e == bi) ? 1.0f : 0.0f);
}

extern "C" void kernel_launch(void* const* d_in, const int* in_sizes, int n_in,
                              void* d_out, int out_size)
{
    const float* q   = (const float*)d_in[0];   // [4096, 128]
    const float* sub = (const float*)d_in[1];   // [4096, 256, 128]
    float*       out = (float*)d_out;           // [4096, 256, 1]

    const int bz = in_sizes[0] / D;             // 4096

    attention_max_kernel<<<bz / 2, 512>>>(q, sub, out);
}

// round 11
// speedup vs baseline: 1.1010x; 1.1010x over previous
#include <cuda_runtime.h>
#include <cuda_bf16.h>
#include <math_constants.h>

// AttentionMax: correlation[b,s] = <q[b], sub[b,s]>, argmax over s, one-hot out [bz, ns, 1]
// bz=4096, ns=256, d=128, fp32. Memory-bound: 512MB compulsory stream of feat_sub.
//
// FINAL (= R9, best measured: ncu 78.7us, DRAM 87.2%, 6.91 TB/s):
//  - warp-cooperative rows: lane l owns float4 chunk l of each 512B row
//    (fully coalesced; R1's per-thread rows saturated L1tex at 91.5%)
//  - software-pipelined 4-row double buffer + 8-row deep prologue
//  - multi-row shuffle reduction (6 shfls per 4 rows)
//  - L2::256B evict-first streaming loads, streaming one-hot stores
//  - 256-thread CTAs, 4 CTA/SM, greedy 4096-CTA dispatch
// Converged at the B300 LTS path cap; persistence (R4), higher occupancy (R5),
// warp decoupling (R6), smaller (R7) and larger (R10) CTAs all regressed.

#define NS 256
#define D  128

// Streaming load with 256B L2 fetch granularity (evict-first policy).
__device__ __forceinline__ float4 ldcs256(const float4* p)
{
    float4 v;
    asm("ld.global.cs.L2::256B.v4.f32 {%0,%1,%2,%3}, [%4];"
        : "=f"(v.x), "=f"(v.y), "=f"(v.z), "=f"(v.w)
        : "l"(p));
    return v;
}

// Streaming store (evict-first): output is write-once, never re-read.
__device__ __forceinline__ void stcs(float* p, float v)
{
    asm volatile("st.global.cs.f32 [%0], %1;" :: "l"(p), "f"(v) : "memory");
}

// Fold 4 rows' per-lane partials into full row sums.
// Result: lane L holds sum of row base + ((L>>3)&3), replicated across 8 lanes.
__device__ __forceinline__ float reduce4(float p0, float p1, float p2, float p3,
                                         int lane)
{
    const unsigned FULL = 0xffffffffu;
    bool hi16 = (lane & 16) != 0;
    float s0 = hi16 ? p0 : p2;
    float s1 = hi16 ? p1 : p3;
    float r0 = __shfl_xor_sync(FULL, s0, 16);
    float r1 = __shfl_xor_sync(FULL, s1, 16);
    float a0 = (hi16 ? p2 : p0) + r0;
    float a1 = (hi16 ? p3 : p1) + r1;
    bool hi8 = (lane & 8) != 0;
    float s = hi8 ? a0 : a1;
    float r = __shfl_xor_sync(FULL, s, 8);
    float acc = (hi8 ? a1 : a0) + r;
    acc += __shfl_xor_sync(FULL, acc, 4);
    acc += __shfl_xor_sync(FULL, acc, 2);
    acc += __shfl_xor_sync(FULL, acc, 1);
    return acc;
}

__device__ __forceinline__ float dot4(float4 v, float4 q)
{
    float p = v.x * q.x;
    p = fmaf(v.y, q.y, p);
    p = fmaf(v.z, q.z, p);
    p = fmaf(v.w, q.w, p);
    return p;
}

__global__ __launch_bounds__(256, 4)
void attention_max_kernel(const float* __restrict__ q,
                          const float* __restrict__ sub,
                          float* __restrict__ out)
{
    const int b    = blockIdx.x;
    const int tid  = threadIdx.x;
    const int warp = tid >> 5;        // 0..7, each warp owns 32 support rows
    const int lane = tid & 31;
    const int myrow = (lane >> 3) & 3;
    const unsigned FULL = 0xffffffffu;

    const float4* base = reinterpret_cast<const float4*>(
        sub + ((size_t)b * NS + warp * 32) * D);

    // Deep prologue: 8 row-loads in flight before any dependent work.
    float4 va[4], vb[4];
#pragma unroll
    for (int j = 0; j < 4; ++j)
        va[j] = ldcs256(&base[j * 32 + lane]);
#pragma unroll
    for (int j = 0; j < 4; ++j)
        vb[j] = ldcs256(&base[(4 + j) * 32 + lane]);

    const float4 qc = reinterpret_cast<const float4*>(q + (size_t)b * D)[lane];

    float bestv = -CUDART_INF_F;
    int   besti = 0;

#pragma unroll
    for (int rr = 0; rr < 32; rr += 8) {
        {
            float s = reduce4(dot4(va[0], qc), dot4(va[1], qc),
                              dot4(va[2], qc), dot4(va[3], qc), lane);
            if (s > bestv) { bestv = s; besti = warp * 32 + rr + myrow; }
        }

        if (rr + 8 < 32) {
#pragma unroll
            for (int j = 0; j < 4; ++j)
                va[j] = ldcs256(&base[(rr + 8 + j) * 32 + lane]);
        }

        {
            float s = reduce4(dot4(vb[0], qc), dot4(vb[1], qc),
                              dot4(vb[2], qc), dot4(vb[3], qc), lane);
            if (s > bestv) { bestv = s; besti = warp * 32 + rr + 4 + myrow; }
        }

        if (rr + 8 < 32) {
#pragma unroll
            for (int j = 0; j < 4; ++j)
                vb[j] = ldcs256(&base[(rr + 12 + j) * 32 + lane]);
        }
    }

    // Cross-lane argmax (value max, smaller index wins ties -> first occurrence).
#pragma unroll
    for (int m = 16; m > 0; m >>= 1) {
        float ov = __shfl_xor_sync(FULL, bestv, m);
        int   oi = __shfl_xor_sync(FULL, besti, m);
        if (ov > bestv || (ov == bestv && oi < besti)) { bestv = ov; besti = oi; }
    }

    __shared__ float wval[8];
    __shared__ int   widx[8];

    if (lane == 0) { wval[warp] = bestv; widx[warp] = besti; }
    __syncthreads();

    // Every thread redundantly reduces the 8 warp results (no second barrier).
    float bv = wval[0];
    int   bi = widx[0];
#pragma unroll
    for (int w = 1; w < 8; ++w)
        if (wval[w] > bv) { bv = wval[w]; bi = widx[w]; }

    stcs(out + (size_t)b * NS + tid, (tid == bi) ? 1.0f : 0.0f);
}

extern "C" void kernel_launch(void* const* d_in, const int* in_sizes, int n_in,
                              void* d_out, int out_size)
{
    const float* q   = (const float*)d_in[0];   // [4096, 128]
    const float* sub = (const float*)d_in[1];   // [4096, 256, 128]
    float*       out = (float*)d_out;           // [4096, 256, 1]

    const int bz = in_sizes[0] / D;             // 4096

    attention_max_kernel<<<bz, NS>>>(q, sub, out);
}